// round 15
// baseline (speedup 1.0000x reference)
#include <cuda_runtime.h>
#include <cuda_fp16.h>
#include <math.h>
#include <stdint.h>

#define EMB   1024
#define DK    64
#define BATCH 4
#define SEQ   4096
#define MROWS (BATCH * SEQ)   // 16384
#define NSPLIT 2
#define KEYS_PER_SPLIT (SEQ / NSPLIT)   // 2048
#define NTILES (KEYS_PER_SPLIT / 64)    // 32

// ---------------- scratch (allocation-free) ----------------
__device__ __align__(128) __half g_q[MROWS * DK];    // [row][d], pre-scaled by 0.125*log2e
__device__ __align__(128) __half g_k[MROWS * DK];    // [row][d]
__device__ __align__(128) __half g_vt[DK * MROWS];   // [d][row]
__device__ __align__(128) __half g_wt[3 * DK * EMB]; // W^T fp16: [which][n][k]
__device__ __align__(128) float  g_po[NSPLIT * MROWS * DK];
__device__ float g_pm[NSPLIT * MROWS];
__device__ float g_pl[NSPLIT * MROWS];

// ---------------- helpers ----------------
__device__ __forceinline__ uint32_t packh2(float x, float y) {
    uint32_t r;
    asm("cvt.rn.f16x2.f32 %0, %1, %2;" : "=r"(r) : "f"(y), "f"(x));
    return r;
}
__device__ __forceinline__ uint32_t smem_u32(const void* p) {
    uint32_t a;
    asm("{ .reg .u64 t; cvta.to.shared.u64 t, %1; cvt.u32.u64 %0, t; }" : "=r"(a) : "l"(p));
    return a;
}
__device__ __forceinline__ void cpa16(uint32_t s, const void* g) {
    asm volatile("cp.async.cg.shared.global [%0], [%1], 16;" :: "r"(s), "l"(g));
}
__device__ __forceinline__ void ldm_x4(uint32_t& r0, uint32_t& r1,
                                       uint32_t& r2, uint32_t& r3, uint32_t addr) {
    asm volatile("ldmatrix.sync.aligned.m8n8.x4.shared.b16 {%0,%1,%2,%3}, [%4];"
                 : "=r"(r0), "=r"(r1), "=r"(r2), "=r"(r3) : "r"(addr));
}
// fp16: D(16x8) += A(16x16) * B(16x8), fp32 accum
__device__ __forceinline__ void mma16(float* c, const uint32_t* a,
                                      uint32_t b0, uint32_t b1) {
    asm volatile(
        "mma.sync.aligned.m16n8k16.row.col.f32.f16.f16.f32 "
        "{%0,%1,%2,%3}, {%4,%5,%6,%7}, {%8,%9}, {%0,%1,%2,%3};"
        : "+f"(c[0]), "+f"(c[1]), "+f"(c[2]), "+f"(c[3])
        : "r"(a[0]), "r"(a[1]), "r"(a[2]), "r"(a[3]), "r"(b0), "r"(b1));
}

#define QSCALE 0.18033688f   // 0.125 * log2(e): softmax done in exp2 domain

// ============================================================
// prep_w: W[1024,64] fp32 -> g_wt[which][n][k] fp16 (once)
// ============================================================
__global__ __launch_bounds__(256) void prep_w(
    const float* __restrict__ Wq, const float* __restrict__ Wk,
    const float* __restrict__ Wv)
{
    const int idx = blockIdx.x * 256 + threadIdx.x;  // 49152
    const int which = idx >> 14;
    const int n  = (idx >> 8) & 63;
    const int k4 = (idx & 255) * 4;
    const float* W = (which == 0) ? Wq : (which == 1 ? Wk : Wv);
    uint2 p;
    p.x = packh2(W[(size_t)(k4 + 0) * DK + n], W[(size_t)(k4 + 1) * DK + n]);
    p.y = packh2(W[(size_t)(k4 + 2) * DK + n], W[(size_t)(k4 + 3) * DK + n]);
    *(uint2*)(g_wt + ((size_t)which * DK + n) * EMB + k4) = p;
}

// ============================================================
// Fused projection: z=0 -> Q (N=64); z=1 -> K|V (N=128)
// BM=128, BK=64, 256 thr, double-buffered X & W, ONE barrier/tile.
// ============================================================
#define XP  72
#define XPB 144
#define XTILE_B (128 * XPB)   // 18432
#define PROJ_SMEM (4 * XTILE_B)

template<int NT>
__device__ __forceinline__ void proj_body(
    const float* __restrict__ X, char* smbase,
    int which, int m0, int tid, int warp, int lane,
    const float* __restrict__ bq, const float* __restrict__ bk,
    const float* __restrict__ bv)
{
    const int g  = lane >> 2;
    const int t4 = lane & 3;
    const int wm = warp * 16;

    __half* Xs[2] = {(__half*)smbase, (__half*)(smbase + XTILE_B)};
    __half* Ws[2] = {(__half*)(smbase + 2 * XTILE_B), (__half*)(smbase + 3 * XTILE_B)};
    const uint32_t xs_s[2] = {smem_u32(Xs[0]), smem_u32(Xs[1])};
    const uint32_t ws_s[2] = {smem_u32(Ws[0]), smem_u32(Ws[1])};

    // ldmatrix lane decomposition
    const int lr = lane & 7;
    const int lh = (lane >> 3) & 1;
    const int lp = lane >> 4;
    const uint32_t a_off = (uint32_t)(wm + lh * 8 + lr) * XPB + lp * 16;
    const uint32_t b_off = (uint32_t)(lp * 8 + lr) * XPB + lh * 16;

    float acc[NT][4];
    #pragma unroll
    for (int nt = 0; nt < NT; nt++)
        #pragma unroll
        for (int j = 0; j < 4; j++) acc[nt][j] = 0.f;

    // W^T tile copy via cp.async into stage st at k-offset kt
    auto issue_w = [&](int kt, int st) {
        #pragma unroll
        for (int it = 0; it < NT / 4; it++) {   // NT*64 uint4 over 256 thr
            int i = tid + it * 256;
            int r = i >> 3, c = i & 7;
            int wsel = (which == 0) ? 0 : (r < 64 ? 1 : 2);
            const __half* src = g_wt + ((size_t)wsel * DK + (r & 63)) * EMB + kt + c * 8;
            cpa16(ws_s[st] + r * XPB + c * 16, src);
        }
        asm volatile("cp.async.commit_group;" ::: "memory");
    };
    // store xp regs into X stage st
    uint2 xp[8];
    auto store_x = [&](int st) {
        #pragma unroll
        for (int it = 0; it < 8; it++) {
            int idx = tid + it * 256;
            int r = idx >> 4, c4 = (idx & 15) * 4;
            *(uint2*)((char*)Xs[st] + r * XPB + c4 * 2) = xp[it];
        }
    };
    auto load_x = [&](int kt) {
        #pragma unroll
        for (int it = 0; it < 8; it++) {
            int idx = tid + it * 256;
            int r = idx >> 4, c4 = (idx & 15) * 4;
            float4 v = *(const float4*)(X + (size_t)(m0 + r) * EMB + kt + c4);
            xp[it].x = packh2(v.x, v.y);
            xp[it].y = packh2(v.z, v.w);
        }
    };

    // ---- prologue: stage 0 = tile 0; prefetch X tile 1 ----
    load_x(0);
    store_x(0);
    issue_w(0, 0);
    load_x(64);
    asm volatile("cp.async.wait_group 0;" ::: "memory");
    __syncthreads();

    #pragma unroll 1
    for (int t = 0; t < EMB / 64; t++) {
        const int st = t & 1;
        // fill stage st^1 with tile t+1 (buffer freed by barrier at end of t-1)
        if (t + 1 < EMB / 64) {
            store_x(st ^ 1);
            issue_w((t + 1) * 64, st ^ 1);
            if (t + 2 < EMB / 64) load_x((t + 2) * 64);
        }

        // ---- compute tile t from stage st ----
        const uint32_t a_lane = xs_s[st] + a_off;
        const uint32_t b_lane = ws_s[st] + b_off;
        #pragma unroll
        for (int ks = 0; ks < 4; ks++) {
            uint32_t a[4];
            ldm_x4(a[0], a[1], a[2], a[3], a_lane + ks * 32);
            #pragma unroll
            for (int ntp = 0; ntp < NT / 2; ntp++) {
                uint32_t b00, b01, b10, b11;
                ldm_x4(b00, b01, b10, b11, b_lane + ntp * (16 * XPB) + ks * 32);
                mma16(acc[ntp * 2    ], a, b00, b01);
                mma16(acc[ntp * 2 + 1], a, b10, b11);
            }
        }
        if (t + 1 < EMB / 64)
            asm volatile("cp.async.wait_group 0;" ::: "memory");
        __syncthreads();
    }

    // ---- epilogue ----
    #pragma unroll
    for (int nt = 0; nt < NT; nt++) {
        const int col = (nt & 7) * 8 + 2 * t4;
        const int rowA = m0 + wm + g, rowB = rowA + 8;
        if (which == 0) {
            const float b0 = bq[col], b1 = bq[col + 1];
            float a0 = (acc[nt][0] + b0) * QSCALE, a1 = (acc[nt][1] + b1) * QSCALE;
            float a2 = (acc[nt][2] + b0) * QSCALE, a3 = (acc[nt][3] + b1) * QSCALE;
            *(uint32_t*)(g_q + (size_t)rowA * DK + col) = packh2(a0, a1);
            *(uint32_t*)(g_q + (size_t)rowB * DK + col) = packh2(a2, a3);
        } else if (nt < 8) {
            const float b0 = bk[col], b1 = bk[col + 1];
            *(uint32_t*)(g_k + (size_t)rowA * DK + col) = packh2(acc[nt][0] + b0, acc[nt][1] + b1);
            *(uint32_t*)(g_k + (size_t)rowB * DK + col) = packh2(acc[nt][2] + b0, acc[nt][3] + b1);
        } else {
            const float b0 = bv[col], b1 = bv[col + 1];
            g_vt[(size_t)(col    ) * MROWS + rowA] = __float2half_rn(acc[nt][0] + b0);
            g_vt[(size_t)(col + 1) * MROWS + rowA] = __float2half_rn(acc[nt][1] + b1);
            g_vt[(size_t)(col    ) * MROWS + rowB] = __float2half_rn(acc[nt][2] + b0);
            g_vt[(size_t)(col + 1) * MROWS + rowB] = __float2half_rn(acc[nt][3] + b1);
        }
    }
}

__global__ __launch_bounds__(256) void proj_fused(
    const float* __restrict__ in1, const float* __restrict__ in2,
    const float* __restrict__ bq, const float* __restrict__ bk,
    const float* __restrict__ bv)
{
    extern __shared__ __align__(16) char smbase[];
    const int which = blockIdx.z;
    const float* X = (which == 0) ? in2 : in1;
    const int m0   = blockIdx.x * 128;
    const int tid  = threadIdx.x;
    const int warp = tid >> 5;
    const int lane = tid & 31;

    if (which == 0)
        proj_body<8>(X, smbase, 0, m0, tid, warp, lane, bq, bk, bv);
    else
        proj_body<16>(X, smbase, 1, m0, tid, warp, lane, bq, bk, bv);
}

// ============================================================
// Flash attention, fp16 m16n8k16, split-KV x2 (single wave),
// cp.async 2-stage, ldmatrix B-fragments, ONE barrier per tile.
// ============================================================
#define FP 88
#define FPB 176

__global__ __launch_bounds__(128) void flash_fp16()
{
    __shared__ __align__(16) __half Ks[2][64 * FP];   // [key][d]
    __shared__ __align__(16) __half Vs[2][64 * FP];   // [d][key]

    const int tid  = threadIdx.x;
    const int warp = tid >> 5;
    const int lane = tid & 31;
    const int g    = lane >> 2;
    const int t4   = lane & 3;
    const int b    = blockIdx.y;
    const int sp   = blockIdx.z;
    const int q0   = blockIdx.x * 64 + warp * 16;
    const int kt0  = sp * KEYS_PER_SPLIT;

    const uint32_t ks_s[2] = {smem_u32(Ks[0]), smem_u32(Ks[1])};
    const uint32_t vs_s[2] = {smem_u32(Vs[0]), smem_u32(Vs[1])};
    const __half* Kg0 = g_k + (size_t)(b * SEQ) * DK;

    // ldmatrix lane decomposition
    const int lr = lane & 7;
    const int lh = (lane >> 3) & 1;
    const int lp = lane >> 4;
    const uint32_t lm_off = (uint32_t)(lp * 8 + lr) * FPB + lh * 16;

    auto issue_tile = [&](int kt, int st) {
        const char* Kg = (const char*)(Kg0 + (size_t)kt * DK);
        const char* Vg = (const char*)(g_vt + (size_t)(b * SEQ + kt));
        #pragma unroll
        for (int it = 0; it < 4; it++) {
            int i = tid + it * 128;
            int r = i >> 3, c = i & 7;
            cpa16(ks_s[st] + r * FPB + c * 16, Kg + r * 128 + c * 16);
            cpa16(vs_s[st] + r * FPB + c * 16, Vg + (size_t)r * (MROWS * 2) + c * 16);
        }
        asm volatile("cp.async.commit_group;" ::: "memory");
    };

    issue_tile(kt0, 0);

    uint32_t q[16];
    {
        const __half* Qg = g_q + (size_t)(b * SEQ + q0) * DK;
        #pragma unroll
        for (int ks = 0; ks < 4; ks++) {
            q[ks * 4 + 0] = *(const uint32_t*)(Qg + (size_t)(g    ) * DK + ks * 16 + 2 * t4    );
            q[ks * 4 + 1] = *(const uint32_t*)(Qg + (size_t)(g + 8) * DK + ks * 16 + 2 * t4    );
            q[ks * 4 + 2] = *(const uint32_t*)(Qg + (size_t)(g    ) * DK + ks * 16 + 2 * t4 + 8);
            q[ks * 4 + 3] = *(const uint32_t*)(Qg + (size_t)(g + 8) * DK + ks * 16 + 2 * t4 + 8);
        }
    }

    float o[8][4];
    #pragma unroll
    for (int nt = 0; nt < 8; nt++)
        #pragma unroll
        for (int j = 0; j < 4; j++) o[nt][j] = 0.f;
    float mA = -INFINITY, mB = -INFINITY, lA = 0.f, lB = 0.f;

    #pragma unroll 1
    for (int t = 0; t < NTILES; t++) {
        const int st = t & 1;
        asm volatile("cp.async.wait_group 0;" ::: "memory");
        __syncthreads();   // tile t visible; all warps done with tile t-1's buffer
        if (t + 1 < NTILES)
            issue_tile(kt0 + (t + 1) * 64, st ^ 1);

        const uint32_t kb_lane = ks_s[st] + lm_off;
        const uint32_t vb_lane = vs_s[st] + lm_off;

        // ---- S = Q @ K^T ----
        float s[8][4];
        #pragma unroll
        for (int nt = 0; nt < 8; nt++)
            #pragma unroll
            for (int j = 0; j < 4; j++) s[nt][j] = 0.f;

        #pragma unroll
        for (int ks = 0; ks < 4; ks++) {
            #pragma unroll
            for (int ntp = 0; ntp < 4; ntp++) {
                uint32_t b00, b01, b10, b11;
                ldm_x4(b00, b01, b10, b11, kb_lane + ntp * (16 * FPB) + ks * 32);
                mma16(s[ntp * 2    ], &q[ks * 4], b00, b01);
                mma16(s[ntp * 2 + 1], &q[ks * 4], b10, b11);
            }
        }

        // ---- online softmax (exp2 domain) ----
        float mxA = -INFINITY, mxB = -INFINITY;
        #pragma unroll
        for (int nt = 0; nt < 8; nt++) {
            mxA = fmaxf(mxA, fmaxf(s[nt][0], s[nt][1]));
            mxB = fmaxf(mxB, fmaxf(s[nt][2], s[nt][3]));
        }
        mxA = fmaxf(mxA, __shfl_xor_sync(0xffffffffu, mxA, 1));
        mxA = fmaxf(mxA, __shfl_xor_sync(0xffffffffu, mxA, 2));
        mxB = fmaxf(mxB, __shfl_xor_sync(0xffffffffu, mxB, 1));
        mxB = fmaxf(mxB, __shfl_xor_sync(0xffffffffu, mxB, 2));

        const float mnA = fmaxf(mA, mxA), mnB = fmaxf(mB, mxB);
        const float cA = exp2f(mA - mnA), cB = exp2f(mB - mnB);

        float sumA = 0.f, sumB = 0.f;
        #pragma unroll
        for (int nt = 0; nt < 8; nt++) {
            s[nt][0] = exp2f(s[nt][0] - mnA);
            s[nt][1] = exp2f(s[nt][1] - mnA);
            s[nt][2] = exp2f(s[nt][2] - mnB);
            s[nt][3] = exp2f(s[nt][3] - mnB);
            sumA += s[nt][0] + s[nt][1];
            sumB += s[nt][2] + s[nt][3];
        }
        sumA += __shfl_xor_sync(0xffffffffu, sumA, 1);
        sumA += __shfl_xor_sync(0xffffffffu, sumA, 2);
        sumB += __shfl_xor_sync(0xffffffffu, sumB, 1);
        sumB += __shfl_xor_sync(0xffffffffu, sumB, 2);
        lA = lA * cA + sumA;  mA = mnA;
        lB = lB * cB + sumB;  mB = mnB;

        #pragma unroll
        for (int nt = 0; nt < 8; nt++) {
            o[nt][0] *= cA; o[nt][1] *= cA;
            o[nt][2] *= cB; o[nt][3] *= cB;
        }

        // ---- O += P @ V ----
        #pragma unroll
        for (int ks = 0; ks < 4; ks++) {
            uint32_t a[4];
            a[0] = packh2(s[2 * ks    ][0], s[2 * ks    ][1]);
            a[1] = packh2(s[2 * ks    ][2], s[2 * ks    ][3]);
            a[2] = packh2(s[2 * ks + 1][0], s[2 * ks + 1][1]);
            a[3] = packh2(s[2 * ks + 1][2], s[2 * ks + 1][3]);
            #pragma unroll
            for (int ntp = 0; ntp < 4; ntp++) {
                uint32_t b00, b01, b10, b11;
                ldm_x4(b00, b01, b10, b11, vb_lane + ntp * (16 * FPB) + ks * 32);
                mma16(o[ntp * 2    ], a, b00, b01);
                mma16(o[ntp * 2 + 1], a, b10, b11);
            }
        }
    }

    // ---- epilogue: unnormalized partials ----
    const int rowA = b * SEQ + q0 + g;
    const int rowB = rowA + 8;
    float* poA = g_po + ((size_t)sp * MROWS + rowA) * DK;
    float* poB = g_po + ((size_t)sp * MROWS + rowB) * DK;
    #pragma unroll
    for (int nt = 0; nt < 8; nt++) {
        const int col = nt * 8 + 2 * t4;
        *(float2*)(poA + col) = make_float2(o[nt][0], o[nt][1]);
        *(float2*)(poB + col) = make_float2(o[nt][2], o[nt][3]);
    }
    if (t4 == 0) {
        g_pm[sp * MROWS + rowA] = mA;  g_pl[sp * MROWS + rowA] = lA;
        g_pm[sp * MROWS + rowB] = mB;  g_pl[sp * MROWS + rowB] = lB;
    }
}

// ============================================================
// Merge NSPLIT partials -> final normalized output (exp2 domain)
// ============================================================
__global__ __launch_bounds__(256) void merge_splits(float* __restrict__ out)
{
    const int i = blockIdx.x * 256 + threadIdx.x;
    const int row = i >> 4, c4 = (i & 15) * 4;

    float m = -INFINITY;
    #pragma unroll
    for (int s = 0; s < NSPLIT; s++)
        m = fmaxf(m, g_pm[s * MROWS + row]);

    float lsum = 0.f;
    float4 acc = {0.f, 0.f, 0.f, 0.f};
    #pragma unroll
    for (int s = 0; s < NSPLIT; s++) {
        const float w = exp2f(g_pm[s * MROWS + row] - m);
        lsum += w * g_pl[s * MROWS + row];
        const float4 o = *(const float4*)(g_po + ((size_t)s * MROWS + row) * DK + c4);
        acc.x += w * o.x; acc.y += w * o.y;
        acc.z += w * o.z; acc.w += w * o.w;
    }
    const float inv = 1.f / lsum;
    float4 r = {acc.x * inv, acc.y * inv, acc.z * inv, acc.w * inv};
    *(float4*)(out + (size_t)row * DK + c4) = r;
}

// ---------------- launch ----------------
extern "C" void kernel_launch(void* const* d_in, const int* in_sizes, int n_in,
                              void* d_out, int out_size)
{
    const float* input1 = (const float*)d_in[0];
    const float* input2 = (const float*)d_in[1];
    const float* Wq = (const float*)d_in[2];
    const float* bq = (const float*)d_in[3];
    const float* Wk = (const float*)d_in[4];
    const float* bk = (const float*)d_in[5];
    const float* Wv = (const float*)d_in[6];
    const float* bv = (const float*)d_in[7];
    float* out = (float*)d_out;

    (void)in_sizes; (void)n_in; (void)out_size;

    prep_w<<<192, 256>>>(Wq, Wk, Wv);

    cudaFuncSetAttribute(proj_fused, cudaFuncAttributeMaxDynamicSharedMemorySize, PROJ_SMEM);
    dim3 pgrid(MROWS / 128, 1, 2);
    proj_fused<<<pgrid, 256, PROJ_SMEM>>>(input1, input2, bq, bk, bv);

    dim3 fgrid(SEQ / 64, BATCH, NSPLIT);
    flash_fp16<<<fgrid, 128>>>();

    merge_splits<<<(MROWS * 16) / 256, 256>>>(out);
}

// round 16
// speedup vs baseline: 1.0530x; 1.0530x over previous
#include <cuda_runtime.h>
#include <cuda_fp16.h>
#include <math.h>
#include <stdint.h>

#define EMB   1024
#define DK    64
#define BATCH 4
#define SEQ   4096
#define MROWS (BATCH * SEQ)   // 16384
#define NSPLIT 4
#define KEYS_PER_SPLIT (SEQ / NSPLIT)   // 1024
#define NTILES (KEYS_PER_SPLIT / 64)    // 16

// ---------------- scratch (allocation-free) ----------------
__device__ __align__(128) __half g_q[MROWS * DK];    // [row][d], pre-scaled by 0.125*log2e
__device__ __align__(128) __half g_k[MROWS * DK];    // [row][d]
__device__ __align__(128) __half g_vt[DK * MROWS];   // [d][row]
__device__ __align__(128) __half g_wt[3 * DK * EMB]; // W^T fp16: [which][n][k]
__device__ __align__(128) float  g_po[NSPLIT * MROWS * DK];
__device__ float g_pm[NSPLIT * MROWS];
__device__ float g_pl[NSPLIT * MROWS];

// ---------------- helpers ----------------
__device__ __forceinline__ uint32_t packh2(float x, float y) {
    uint32_t r;
    asm("cvt.rn.f16x2.f32 %0, %1, %2;" : "=r"(r) : "f"(y), "f"(x));
    return r;
}
__device__ __forceinline__ uint32_t smem_u32(const void* p) {
    uint32_t a;
    asm("{ .reg .u64 t; cvta.to.shared.u64 t, %1; cvt.u32.u64 %0, t; }" : "=r"(a) : "l"(p));
    return a;
}
__device__ __forceinline__ void cpa16(uint32_t s, const void* g) {
    asm volatile("cp.async.cg.shared.global [%0], [%1], 16;" :: "r"(s), "l"(g));
}
__device__ __forceinline__ void ldm_x4(uint32_t& r0, uint32_t& r1,
                                       uint32_t& r2, uint32_t& r3, uint32_t addr) {
    asm volatile("ldmatrix.sync.aligned.m8n8.x4.shared.b16 {%0,%1,%2,%3}, [%4];"
                 : "=r"(r0), "=r"(r1), "=r"(r2), "=r"(r3) : "r"(addr));
}
// fp16: D(16x8) += A(16x16) * B(16x8), fp32 accum
__device__ __forceinline__ void mma16(float* c, const uint32_t* a,
                                      uint32_t b0, uint32_t b1) {
    asm volatile(
        "mma.sync.aligned.m16n8k16.row.col.f32.f16.f16.f32 "
        "{%0,%1,%2,%3}, {%4,%5,%6,%7}, {%8,%9}, {%0,%1,%2,%3};"
        : "+f"(c[0]), "+f"(c[1]), "+f"(c[2]), "+f"(c[3])
        : "r"(a[0]), "r"(a[1]), "r"(a[2]), "r"(a[3]), "r"(b0), "r"(b1));
}

#define QSCALE 0.18033688f   // 0.125 * log2(e): softmax done in exp2 domain

// ============================================================
// prep_w: W[1024,64] fp32 -> g_wt[which][n][k] fp16 (once)
// ============================================================
__global__ __launch_bounds__(256) void prep_w(
    const float* __restrict__ Wq, const float* __restrict__ Wk,
    const float* __restrict__ Wv)
{
    const int idx = blockIdx.x * 256 + threadIdx.x;  // 49152
    const int which = idx >> 14;
    const int n  = (idx >> 8) & 63;
    const int k4 = (idx & 255) * 4;
    const float* W = (which == 0) ? Wq : (which == 1 ? Wk : Wv);
    uint2 p;
    p.x = packh2(W[(size_t)(k4 + 0) * DK + n], W[(size_t)(k4 + 1) * DK + n]);
    p.y = packh2(W[(size_t)(k4 + 2) * DK + n], W[(size_t)(k4 + 3) * DK + n]);
    *(uint2*)(g_wt + ((size_t)which * DK + n) * EMB + k4) = p;
}

// ============================================================
// Fused projection: z=0 -> Q (N=64); z=1 -> K|V (N=128)
// BM=128, BK=64, 256 thr, A-frags straight from global (no X smem),
// W cp.async double-buffered, ONE barrier per tile, 2 CTAs/SM.
// ============================================================
#define XPB 144                      // W smem pitch in bytes
#define WTILE_B (128 * XPB)          // 18432
#define PROJ_SMEM_ST (2 * WTILE_B)   // 36864 static

template<int NT>
__device__ __forceinline__ void proj_body(
    const float* __restrict__ X, char* smbase,
    int which, int m0, int tid, int warp, int lane,
    const float* __restrict__ bq, const float* __restrict__ bk,
    const float* __restrict__ bv)
{
    const int g  = lane >> 2;
    const int t4 = lane & 3;
    const int wm = warp * 16;

    const uint32_t ws_s[2] = {smem_u32(smbase), smem_u32(smbase + WTILE_B)};

    // ldmatrix B lane decomposition
    const int lr = lane & 7;
    const int lh = (lane >> 3) & 1;
    const int lp = lane >> 4;
    const uint32_t b_off = (uint32_t)(lp * 8 + lr) * XPB + lh * 16;

    // A-frag global row bases for this thread
    const float* xr0 = X + (size_t)(m0 + wm + g) * EMB + 2 * t4;
    const float* xr1 = xr0 + (size_t)8 * EMB;

    float acc[NT][4];
    #pragma unroll
    for (int nt = 0; nt < NT; nt++)
        #pragma unroll
        for (int j = 0; j < 4; j++) acc[nt][j] = 0.f;

    // W^T tile cp.async into stage st (NT*8 rows x 8 uint4 over 256 thr)
    auto issue_w = [&](int kt, int st) {
        #pragma unroll
        for (int it = 0; it < NT / 4; it++) {
            int i = tid + it * 256;
            int r = i >> 3, c = i & 7;
            int wsel = (which == 0) ? 0 : (r < 64 ? 1 : 2);
            const __half* src = g_wt + ((size_t)wsel * DK + (r & 63)) * EMB + kt + c * 8;
            cpa16(ws_s[st] + r * XPB + c * 16, src);
        }
        asm volatile("cp.async.commit_group;" ::: "memory");
    };

    issue_w(0, 0);

    #pragma unroll 1
    for (int t = 0; t < EMB / 64; t++) {
        const int st = t & 1;
        asm volatile("cp.async.wait_group 0;" ::: "memory");
        __syncthreads();   // W(t) visible; all warps done reading buffer st^1
        if (t + 1 < EMB / 64)
            issue_w((t + 1) * 64, st ^ 1);

        // ---- A fragments direct from global (fp32 -> fp16 pack) ----
        uint32_t a[4][4];
        #pragma unroll
        for (int ks = 0; ks < 4; ks++) {
            const int col = t * 64 + ks * 16;
            float2 v00 = *(const float2*)(xr0 + col);
            float2 v10 = *(const float2*)(xr1 + col);
            float2 v01 = *(const float2*)(xr0 + col + 8);
            float2 v11 = *(const float2*)(xr1 + col + 8);
            a[ks][0] = packh2(v00.x, v00.y);
            a[ks][1] = packh2(v10.x, v10.y);
            a[ks][2] = packh2(v01.x, v01.y);
            a[ks][3] = packh2(v11.x, v11.y);
        }

        // ---- MMAs from W stage st ----
        const uint32_t b_lane = ws_s[st] + b_off;
        #pragma unroll
        for (int ks = 0; ks < 4; ks++) {
            #pragma unroll
            for (int ntp = 0; ntp < NT / 2; ntp++) {
                uint32_t b00, b01, b10, b11;
                ldm_x4(b00, b01, b10, b11, b_lane + ntp * (16 * XPB) + ks * 32);
                mma16(acc[ntp * 2    ], a[ks], b00, b01);
                mma16(acc[ntp * 2 + 1], a[ks], b10, b11);
            }
        }
    }

    // ---- epilogue ----
    #pragma unroll
    for (int nt = 0; nt < NT; nt++) {
        const int col = (nt & 7) * 8 + 2 * t4;
        const int rowA = m0 + wm + g, rowB = rowA + 8;
        if (which == 0) {
            const float b0 = bq[col], b1 = bq[col + 1];
            float a0 = (acc[nt][0] + b0) * QSCALE, a1 = (acc[nt][1] + b1) * QSCALE;
            float a2 = (acc[nt][2] + b0) * QSCALE, a3 = (acc[nt][3] + b1) * QSCALE;
            *(uint32_t*)(g_q + (size_t)rowA * DK + col) = packh2(a0, a1);
            *(uint32_t*)(g_q + (size_t)rowB * DK + col) = packh2(a2, a3);
        } else if (nt < 8) {
            const float b0 = bk[col], b1 = bk[col + 1];
            *(uint32_t*)(g_k + (size_t)rowA * DK + col) = packh2(acc[nt][0] + b0, acc[nt][1] + b1);
            *(uint32_t*)(g_k + (size_t)rowB * DK + col) = packh2(acc[nt][2] + b0, acc[nt][3] + b1);
        } else {
            const float b0 = bv[col], b1 = bv[col + 1];
            g_vt[(size_t)(col    ) * MROWS + rowA] = __float2half_rn(acc[nt][0] + b0);
            g_vt[(size_t)(col + 1) * MROWS + rowA] = __float2half_rn(acc[nt][1] + b1);
            g_vt[(size_t)(col    ) * MROWS + rowB] = __float2half_rn(acc[nt][2] + b0);
            g_vt[(size_t)(col + 1) * MROWS + rowB] = __float2half_rn(acc[nt][3] + b1);
        }
    }
}

__global__ __launch_bounds__(256, 2) void proj_fused(
    const float* __restrict__ in1, const float* __restrict__ in2,
    const float* __restrict__ bq, const float* __restrict__ bk,
    const float* __restrict__ bv)
{
    __shared__ __align__(16) char smbase[PROJ_SMEM_ST];
    const int which = blockIdx.z;
    const float* X = (which == 0) ? in2 : in1;
    const int m0   = blockIdx.x * 128;
    const int tid  = threadIdx.x;
    const int warp = tid >> 5;
    const int lane = tid & 31;

    if (which == 0)
        proj_body<8>(X, smbase, 0, m0, tid, warp, lane, bq, bk, bv);
    else
        proj_body<16>(X, smbase, 1, m0, tid, warp, lane, bq, bk, bv);
}

// ============================================================
// Flash attention, fp16 m16n8k16, split-KV x4, cp.async 2-stage,
// ldmatrix B-fragments, ONE barrier per tile.  (R14 = 125.7us config)
// ============================================================
#define FP 88
#define FPB 176

__global__ __launch_bounds__(128) void flash_fp16()
{
    __shared__ __align__(16) __half Ks[2][64 * FP];   // [key][d]
    __shared__ __align__(16) __half Vs[2][64 * FP];   // [d][key]

    const int tid  = threadIdx.x;
    const int warp = tid >> 5;
    const int lane = tid & 31;
    const int g    = lane >> 2;
    const int t4   = lane & 3;
    const int b    = blockIdx.y;
    const int sp   = blockIdx.z;
    const int q0   = blockIdx.x * 64 + warp * 16;
    const int kt0  = sp * KEYS_PER_SPLIT;

    const uint32_t ks_s[2] = {smem_u32(Ks[0]), smem_u32(Ks[1])};
    const uint32_t vs_s[2] = {smem_u32(Vs[0]), smem_u32(Vs[1])};
    const __half* Kg0 = g_k + (size_t)(b * SEQ) * DK;

    // ldmatrix lane decomposition
    const int lr = lane & 7;
    const int lh = (lane >> 3) & 1;
    const int lp = lane >> 4;
    const uint32_t lm_off = (uint32_t)(lp * 8 + lr) * FPB + lh * 16;

    auto issue_tile = [&](int kt, int st) {
        const char* Kg = (const char*)(Kg0 + (size_t)kt * DK);
        const char* Vg = (const char*)(g_vt + (size_t)(b * SEQ + kt));
        #pragma unroll
        for (int it = 0; it < 4; it++) {
            int i = tid + it * 128;
            int r = i >> 3, c = i & 7;
            cpa16(ks_s[st] + r * FPB + c * 16, Kg + r * 128 + c * 16);
            cpa16(vs_s[st] + r * FPB + c * 16, Vg + (size_t)r * (MROWS * 2) + c * 16);
        }
        asm volatile("cp.async.commit_group;" ::: "memory");
    };

    issue_tile(kt0, 0);

    uint32_t q[16];
    {
        const __half* Qg = g_q + (size_t)(b * SEQ + q0) * DK;
        #pragma unroll
        for (int ks = 0; ks < 4; ks++) {
            q[ks * 4 + 0] = *(const uint32_t*)(Qg + (size_t)(g    ) * DK + ks * 16 + 2 * t4    );
            q[ks * 4 + 1] = *(const uint32_t*)(Qg + (size_t)(g + 8) * DK + ks * 16 + 2 * t4    );
            q[ks * 4 + 2] = *(const uint32_t*)(Qg + (size_t)(g    ) * DK + ks * 16 + 2 * t4 + 8);
            q[ks * 4 + 3] = *(const uint32_t*)(Qg + (size_t)(g + 8) * DK + ks * 16 + 2 * t4 + 8);
        }
    }

    float o[8][4];
    #pragma unroll
    for (int nt = 0; nt < 8; nt++)
        #pragma unroll
        for (int j = 0; j < 4; j++) o[nt][j] = 0.f;
    float mA = -INFINITY, mB = -INFINITY, lA = 0.f, lB = 0.f;

    #pragma unroll 1
    for (int t = 0; t < NTILES; t++) {
        const int st = t & 1;
        asm volatile("cp.async.wait_group 0;" ::: "memory");
        __syncthreads();   // tile t visible; all warps done with tile t-1's buffer
        if (t + 1 < NTILES)
            issue_tile(kt0 + (t + 1) * 64, st ^ 1);

        const uint32_t kb_lane = ks_s[st] + lm_off;
        const uint32_t vb_lane = vs_s[st] + lm_off;

        // ---- S = Q @ K^T ----
        float s[8][4];
        #pragma unroll
        for (int nt = 0; nt < 8; nt++)
            #pragma unroll
            for (int j = 0; j < 4; j++) s[nt][j] = 0.f;

        #pragma unroll
        for (int ks = 0; ks < 4; ks++) {
            #pragma unroll
            for (int ntp = 0; ntp < 4; ntp++) {
                uint32_t b00, b01, b10, b11;
                ldm_x4(b00, b01, b10, b11, kb_lane + ntp * (16 * FPB) + ks * 32);
                mma16(s[ntp * 2    ], &q[ks * 4], b00, b01);
                mma16(s[ntp * 2 + 1], &q[ks * 4], b10, b11);
            }
        }

        // ---- online softmax (exp2 domain) ----
        float mxA = -INFINITY, mxB = -INFINITY;
        #pragma unroll
        for (int nt = 0; nt < 8; nt++) {
            mxA = fmaxf(mxA, fmaxf(s[nt][0], s[nt][1]));
            mxB = fmaxf(mxB, fmaxf(s[nt][2], s[nt][3]));
        }
        mxA = fmaxf(mxA, __shfl_xor_sync(0xffffffffu, mxA, 1));
        mxA = fmaxf(mxA, __shfl_xor_sync(0xffffffffu, mxA, 2));
        mxB = fmaxf(mxB, __shfl_xor_sync(0xffffffffu, mxB, 1));
        mxB = fmaxf(mxB, __shfl_xor_sync(0xffffffffu, mxB, 2));

        const float mnA = fmaxf(mA, mxA), mnB = fmaxf(mB, mxB);
        const float cA = exp2f(mA - mnA), cB = exp2f(mB - mnB);

        float sumA = 0.f, sumB = 0.f;
        #pragma unroll
        for (int nt = 0; nt < 8; nt++) {
            s[nt][0] = exp2f(s[nt][0] - mnA);
            s[nt][1] = exp2f(s[nt][1] - mnA);
            s[nt][2] = exp2f(s[nt][2] - mnB);
            s[nt][3] = exp2f(s[nt][3] - mnB);
            sumA += s[nt][0] + s[nt][1];
            sumB += s[nt][2] + s[nt][3];
        }
        sumA += __shfl_xor_sync(0xffffffffu, sumA, 1);
        sumA += __shfl_xor_sync(0xffffffffu, sumA, 2);
        sumB += __shfl_xor_sync(0xffffffffu, sumB, 1);
        sumB += __shfl_xor_sync(0xffffffffu, sumB, 2);
        lA = lA * cA + sumA;  mA = mnA;
        lB = lB * cB + sumB;  mB = mnB;

        #pragma unroll
        for (int nt = 0; nt < 8; nt++) {
            o[nt][0] *= cA; o[nt][1] *= cA;
            o[nt][2] *= cB; o[nt][3] *= cB;
        }

        // ---- O += P @ V ----
        #pragma unroll
        for (int ks = 0; ks < 4; ks++) {
            uint32_t a[4];
            a[0] = packh2(s[2 * ks    ][0], s[2 * ks    ][1]);
            a[1] = packh2(s[2 * ks    ][2], s[2 * ks    ][3]);
            a[2] = packh2(s[2 * ks + 1][0], s[2 * ks + 1][1]);
            a[3] = packh2(s[2 * ks + 1][2], s[2 * ks + 1][3]);
            #pragma unroll
            for (int ntp = 0; ntp < 4; ntp++) {
                uint32_t b00, b01, b10, b11;
                ldm_x4(b00, b01, b10, b11, vb_lane + ntp * (16 * FPB) + ks * 32);
                mma16(o[ntp * 2    ], a, b00, b01);
                mma16(o[ntp * 2 + 1], a, b10, b11);
            }
        }
    }

    // ---- epilogue: unnormalized partials ----
    const int rowA = b * SEQ + q0 + g;
    const int rowB = rowA + 8;
    float* poA = g_po + ((size_t)sp * MROWS + rowA) * DK;
    float* poB = g_po + ((size_t)sp * MROWS + rowB) * DK;
    #pragma unroll
    for (int nt = 0; nt < 8; nt++) {
        const int col = nt * 8 + 2 * t4;
        *(float2*)(poA + col) = make_float2(o[nt][0], o[nt][1]);
        *(float2*)(poB + col) = make_float2(o[nt][2], o[nt][3]);
    }
    if (t4 == 0) {
        g_pm[sp * MROWS + rowA] = mA;  g_pl[sp * MROWS + rowA] = lA;
        g_pm[sp * MROWS + rowB] = mB;  g_pl[sp * MROWS + rowB] = lB;
    }
}

// ============================================================
// Merge NSPLIT partials -> final normalized output (exp2 domain)
// ============================================================
__global__ __launch_bounds__(256) void merge_splits(float* __restrict__ out)
{
    const int i = blockIdx.x * 256 + threadIdx.x;
    const int row = i >> 4, c4 = (i & 15) * 4;

    float m = -INFINITY;
    #pragma unroll
    for (int s = 0; s < NSPLIT; s++)
        m = fmaxf(m, g_pm[s * MROWS + row]);

    float lsum = 0.f;
    float4 acc = {0.f, 0.f, 0.f, 0.f};
    #pragma unroll
    for (int s = 0; s < NSPLIT; s++) {
        const float w = exp2f(g_pm[s * MROWS + row] - m);
        lsum += w * g_pl[s * MROWS + row];
        const float4 o = *(const float4*)(g_po + ((size_t)s * MROWS + row) * DK + c4);
        acc.x += w * o.x; acc.y += w * o.y;
        acc.z += w * o.z; acc.w += w * o.w;
    }
    const float inv = 1.f / lsum;
    float4 r = {acc.x * inv, acc.y * inv, acc.z * inv, acc.w * inv};
    *(float4*)(out + (size_t)row * DK + c4) = r;
}

// ---------------- launch ----------------
extern "C" void kernel_launch(void* const* d_in, const int* in_sizes, int n_in,
                              void* d_out, int out_size)
{
    const float* input1 = (const float*)d_in[0];
    const float* input2 = (const float*)d_in[1];
    const float* Wq = (const float*)d_in[2];
    const float* bq = (const float*)d_in[3];
    const float* Wk = (const float*)d_in[4];
    const float* bk = (const float*)d_in[5];
    const float* Wv = (const float*)d_in[6];
    const float* bv = (const float*)d_in[7];
    float* out = (float*)d_out;

    (void)in_sizes; (void)n_in; (void)out_size;

    prep_w<<<192, 256>>>(Wq, Wk, Wv);

    dim3 pgrid(MROWS / 128, 1, 2);
    proj_fused<<<pgrid, 256>>>(input1, input2, bq, bk, bv);

    dim3 fgrid(SEQ / 64, BATCH, NSPLIT);
    flash_fp16<<<fgrid, 128>>>();

    merge_splits<<<(MROWS * 16) / 256, 256>>>(out);
}

// round 17
// speedup vs baseline: 1.1030x; 1.0475x over previous
#include <cuda_runtime.h>
#include <cuda_fp16.h>
#include <math.h>
#include <stdint.h>

#define EMB   1024
#define DK    64
#define BATCH 4
#define SEQ   4096
#define MROWS (BATCH * SEQ)   // 16384
#define NSPLIT 4
#define KEYS_PER_SPLIT (SEQ / NSPLIT)   // 1024
#define NTILES (KEYS_PER_SPLIT / 64)    // 16

// ---------------- scratch (allocation-free) ----------------
__device__ __align__(128) __half g_q[MROWS * DK];    // [row][d], pre-scaled by 0.125*log2e
__device__ __align__(128) __half g_k[MROWS * DK];    // [row][d]
__device__ __align__(128) __half g_vt[DK * MROWS];   // [d][row]
__device__ __align__(128) __half g_wt[3 * DK * EMB]; // W^T fp16: [which][n][k]
__device__ __align__(128) float  g_po[NSPLIT * MROWS * DK];
__device__ float g_pm[NSPLIT * MROWS];
__device__ float g_pl[NSPLIT * MROWS];

// ---------------- helpers ----------------
__device__ __forceinline__ uint32_t packh2(float x, float y) {
    uint32_t r;
    asm("cvt.rn.f16x2.f32 %0, %1, %2;" : "=r"(r) : "f"(y), "f"(x));
    return r;
}
__device__ __forceinline__ uint32_t h2exp2(uint32_t x) {
    uint32_t r;
    asm("ex2.approx.f16x2 %0, %1;" : "=r"(r) : "r"(x));
    return r;
}
__device__ __forceinline__ float2 h2f2(uint32_t x) {
    __half2 h = *(__half2*)&x;
    return __half22float2(h);
}
__device__ __forceinline__ uint32_t smem_u32(const void* p) {
    uint32_t a;
    asm("{ .reg .u64 t; cvta.to.shared.u64 t, %1; cvt.u32.u64 %0, t; }" : "=r"(a) : "l"(p));
    return a;
}
__device__ __forceinline__ void cpa16(uint32_t s, const void* g) {
    asm volatile("cp.async.cg.shared.global [%0], [%1], 16;" :: "r"(s), "l"(g));
}
__device__ __forceinline__ void ldm_x4(uint32_t& r0, uint32_t& r1,
                                       uint32_t& r2, uint32_t& r3, uint32_t addr) {
    asm volatile("ldmatrix.sync.aligned.m8n8.x4.shared.b16 {%0,%1,%2,%3}, [%4];"
                 : "=r"(r0), "=r"(r1), "=r"(r2), "=r"(r3) : "r"(addr));
}
// fp16: D(16x8) += A(16x16) * B(16x8), fp32 accum
__device__ __forceinline__ void mma16(float* c, const uint32_t* a,
                                      uint32_t b0, uint32_t b1) {
    asm volatile(
        "mma.sync.aligned.m16n8k16.row.col.f32.f16.f16.f32 "
        "{%0,%1,%2,%3}, {%4,%5,%6,%7}, {%8,%9}, {%0,%1,%2,%3};"
        : "+f"(c[0]), "+f"(c[1]), "+f"(c[2]), "+f"(c[3])
        : "r"(a[0]), "r"(a[1]), "r"(a[2]), "r"(a[3]), "r"(b0), "r"(b1));
}

#define QSCALE 0.18033688f   // 0.125 * log2(e): softmax done in exp2 domain

// ============================================================
// prep_w: W[1024,64] fp32 -> g_wt[which][n][k] fp16 (once)
// ============================================================
__global__ __launch_bounds__(256) void prep_w(
    const float* __restrict__ Wq, const float* __restrict__ Wk,
    const float* __restrict__ Wv)
{
    const int idx = blockIdx.x * 256 + threadIdx.x;  // 49152
    const int which = idx >> 14;
    const int n  = (idx >> 8) & 63;
    const int k4 = (idx & 255) * 4;
    const float* W = (which == 0) ? Wq : (which == 1 ? Wk : Wv);
    uint2 p;
    p.x = packh2(W[(size_t)(k4 + 0) * DK + n], W[(size_t)(k4 + 1) * DK + n]);
    p.y = packh2(W[(size_t)(k4 + 2) * DK + n], W[(size_t)(k4 + 3) * DK + n]);
    *(uint2*)(g_wt + ((size_t)which * DK + n) * EMB + k4) = p;
}

// ============================================================
// Fused projection (R16 structure): z=0 -> Q (N=64); z=1 -> K|V (N=128)
// BM=128, BK=64, 256 thr, A-frags from global, W cp.async 2-stage.
// ============================================================
#define XPB 144
#define WTILE_B (128 * XPB)
#define PROJ_SMEM_ST (2 * WTILE_B)

template<int NT>
__device__ __forceinline__ void proj_body(
    const float* __restrict__ X, char* smbase,
    int which, int m0, int tid, int warp, int lane,
    const float* __restrict__ bq, const float* __restrict__ bk,
    const float* __restrict__ bv)
{
    const int g  = lane >> 2;
    const int t4 = lane & 3;
    const int wm = warp * 16;

    const uint32_t ws_s[2] = {smem_u32(smbase), smem_u32(smbase + WTILE_B)};

    const int lr = lane & 7;
    const int lh = (lane >> 3) & 1;
    const int lp = lane >> 4;
    const uint32_t b_off = (uint32_t)(lp * 8 + lr) * XPB + lh * 16;

    const float* xr0 = X + (size_t)(m0 + wm + g) * EMB + 2 * t4;
    const float* xr1 = xr0 + (size_t)8 * EMB;

    float acc[NT][4];
    #pragma unroll
    for (int nt = 0; nt < NT; nt++)
        #pragma unroll
        for (int j = 0; j < 4; j++) acc[nt][j] = 0.f;

    auto issue_w = [&](int kt, int st) {
        #pragma unroll
        for (int it = 0; it < NT / 4; it++) {
            int i = tid + it * 256;
            int r = i >> 3, c = i & 7;
            int wsel = (which == 0) ? 0 : (r < 64 ? 1 : 2);
            const __half* src = g_wt + ((size_t)wsel * DK + (r & 63)) * EMB + kt + c * 8;
            cpa16(ws_s[st] + r * XPB + c * 16, src);
        }
        asm volatile("cp.async.commit_group;" ::: "memory");
    };

    issue_w(0, 0);

    #pragma unroll 1
    for (int t = 0; t < EMB / 64; t++) {
        const int st = t & 1;
        asm volatile("cp.async.wait_group 0;" ::: "memory");
        __syncthreads();
        if (t + 1 < EMB / 64)
            issue_w((t + 1) * 64, st ^ 1);

        uint32_t a[4][4];
        #pragma unroll
        for (int ks = 0; ks < 4; ks++) {
            const int col = t * 64 + ks * 16;
            float2 v00 = *(const float2*)(xr0 + col);
            float2 v10 = *(const float2*)(xr1 + col);
            float2 v01 = *(const float2*)(xr0 + col + 8);
            float2 v11 = *(const float2*)(xr1 + col + 8);
            a[ks][0] = packh2(v00.x, v00.y);
            a[ks][1] = packh2(v10.x, v10.y);
            a[ks][2] = packh2(v01.x, v01.y);
            a[ks][3] = packh2(v11.x, v11.y);
        }

        const uint32_t b_lane = ws_s[st] + b_off;
        #pragma unroll
        for (int ks = 0; ks < 4; ks++) {
            #pragma unroll
            for (int ntp = 0; ntp < NT / 2; ntp++) {
                uint32_t b00, b01, b10, b11;
                ldm_x4(b00, b01, b10, b11, b_lane + ntp * (16 * XPB) + ks * 32);
                mma16(acc[ntp * 2    ], a[ks], b00, b01);
                mma16(acc[ntp * 2 + 1], a[ks], b10, b11);
            }
        }
    }

    #pragma unroll
    for (int nt = 0; nt < NT; nt++) {
        const int col = (nt & 7) * 8 + 2 * t4;
        const int rowA = m0 + wm + g, rowB = rowA + 8;
        if (which == 0) {
            const float b0 = bq[col], b1 = bq[col + 1];
            float a0 = (acc[nt][0] + b0) * QSCALE, a1 = (acc[nt][1] + b1) * QSCALE;
            float a2 = (acc[nt][2] + b0) * QSCALE, a3 = (acc[nt][3] + b1) * QSCALE;
            *(uint32_t*)(g_q + (size_t)rowA * DK + col) = packh2(a0, a1);
            *(uint32_t*)(g_q + (size_t)rowB * DK + col) = packh2(a2, a3);
        } else if (nt < 8) {
            const float b0 = bk[col], b1 = bk[col + 1];
            *(uint32_t*)(g_k + (size_t)rowA * DK + col) = packh2(acc[nt][0] + b0, acc[nt][1] + b1);
            *(uint32_t*)(g_k + (size_t)rowB * DK + col) = packh2(acc[nt][2] + b0, acc[nt][3] + b1);
        } else {
            const float b0 = bv[col], b1 = bv[col + 1];
            g_vt[(size_t)(col    ) * MROWS + rowA] = __float2half_rn(acc[nt][0] + b0);
            g_vt[(size_t)(col + 1) * MROWS + rowA] = __float2half_rn(acc[nt][1] + b1);
            g_vt[(size_t)(col    ) * MROWS + rowB] = __float2half_rn(acc[nt][2] + b0);
            g_vt[(size_t)(col + 1) * MROWS + rowB] = __float2half_rn(acc[nt][3] + b1);
        }
    }
}

__global__ __launch_bounds__(256, 2) void proj_fused(
    const float* __restrict__ in1, const float* __restrict__ in2,
    const float* __restrict__ bq, const float* __restrict__ bk,
    const float* __restrict__ bv)
{
    __shared__ __align__(16) char smbase[PROJ_SMEM_ST];
    const int which = blockIdx.z;
    const float* X = (which == 0) ? in2 : in1;
    const int m0   = blockIdx.x * 128;
    const int tid  = threadIdx.x;
    const int warp = tid >> 5;
    const int lane = tid & 31;

    if (which == 0)
        proj_body<8>(X, smbase, 0, m0, tid, warp, lane, bq, bk, bv);
    else
        proj_body<16>(X, smbase, 1, m0, tid, warp, lane, bq, bk, bv);
}

// ============================================================
// Flash attention, fp16 m16n8k16, split-KV x4, cp.async 2-stage,
// ldmatrix B-fragments, ONE barrier per tile, f16x2 exp2 softmax.
// ============================================================
#define FP 88
#define FPB 176

__global__ __launch_bounds__(128) void flash_fp16()
{
    __shared__ __align__(16) __half Ks[2][64 * FP];   // [key][d]
    __shared__ __align__(16) __half Vs[2][64 * FP];   // [d][key]

    const int tid  = threadIdx.x;
    const int warp = tid >> 5;
    const int lane = tid & 31;
    const int g    = lane >> 2;
    const int t4   = lane & 3;
    const int b    = blockIdx.y;
    const int sp   = blockIdx.z;
    const int q0   = blockIdx.x * 64 + warp * 16;
    const int kt0  = sp * KEYS_PER_SPLIT;

    const uint32_t ks_s[2] = {smem_u32(Ks[0]), smem_u32(Ks[1])};
    const uint32_t vs_s[2] = {smem_u32(Vs[0]), smem_u32(Vs[1])};
    const __half* Kg0 = g_k + (size_t)(b * SEQ) * DK;

    const int lr = lane & 7;
    const int lh = (lane >> 3) & 1;
    const int lp = lane >> 4;
    const uint32_t lm_off = (uint32_t)(lp * 8 + lr) * FPB + lh * 16;

    auto issue_tile = [&](int kt, int st) {
        const char* Kg = (const char*)(Kg0 + (size_t)kt * DK);
        const char* Vg = (const char*)(g_vt + (size_t)(b * SEQ + kt));
        #pragma unroll
        for (int it = 0; it < 4; it++) {
            int i = tid + it * 128;
            int r = i >> 3, c = i & 7;
            cpa16(ks_s[st] + r * FPB + c * 16, Kg + r * 128 + c * 16);
            cpa16(vs_s[st] + r * FPB + c * 16, Vg + (size_t)r * (MROWS * 2) + c * 16);
        }
        asm volatile("cp.async.commit_group;" ::: "memory");
    };

    issue_tile(kt0, 0);

    uint32_t q[16];
    {
        const __half* Qg = g_q + (size_t)(b * SEQ + q0) * DK;
        #pragma unroll
        for (int ks = 0; ks < 4; ks++) {
            q[ks * 4 + 0] = *(const uint32_t*)(Qg + (size_t)(g    ) * DK + ks * 16 + 2 * t4    );
            q[ks * 4 + 1] = *(const uint32_t*)(Qg + (size_t)(g + 8) * DK + ks * 16 + 2 * t4    );
            q[ks * 4 + 2] = *(const uint32_t*)(Qg + (size_t)(g    ) * DK + ks * 16 + 2 * t4 + 8);
            q[ks * 4 + 3] = *(const uint32_t*)(Qg + (size_t)(g + 8) * DK + ks * 16 + 2 * t4 + 8);
        }
    }

    float o[8][4];
    #pragma unroll
    for (int nt = 0; nt < 8; nt++)
        #pragma unroll
        for (int j = 0; j < 4; j++) o[nt][j] = 0.f;
    float mA = -INFINITY, mB = -INFINITY, lA = 0.f, lB = 0.f;

    #pragma unroll 1
    for (int t = 0; t < NTILES; t++) {
        const int st = t & 1;
        asm volatile("cp.async.wait_group 0;" ::: "memory");
        __syncthreads();
        if (t + 1 < NTILES)
            issue_tile(kt0 + (t + 1) * 64, st ^ 1);

        const uint32_t kb_lane = ks_s[st] + lm_off;
        const uint32_t vb_lane = vs_s[st] + lm_off;

        // ---- S = Q @ K^T ----
        float s[8][4];
        #pragma unroll
        for (int nt = 0; nt < 8; nt++)
            #pragma unroll
            for (int j = 0; j < 4; j++) s[nt][j] = 0.f;

        #pragma unroll
        for (int ks = 0; ks < 4; ks++) {
            #pragma unroll
            for (int ntp = 0; ntp < 4; ntp++) {
                uint32_t b00, b01, b10, b11;
                ldm_x4(b00, b01, b10, b11, kb_lane + ntp * (16 * FPB) + ks * 32);
                mma16(s[ntp * 2    ], &q[ks * 4], b00, b01);
                mma16(s[ntp * 2 + 1], &q[ks * 4], b10, b11);
            }
        }

        // ---- online softmax: exp in f16x2 (P = PV A-fragments directly) ----
        float mxA = -INFINITY, mxB = -INFINITY;
        #pragma unroll
        for (int nt = 0; nt < 8; nt++) {
            mxA = fmaxf(mxA, fmaxf(s[nt][0], s[nt][1]));
            mxB = fmaxf(mxB, fmaxf(s[nt][2], s[nt][3]));
        }
        mxA = fmaxf(mxA, __shfl_xor_sync(0xffffffffu, mxA, 1));
        mxA = fmaxf(mxA, __shfl_xor_sync(0xffffffffu, mxA, 2));
        mxB = fmaxf(mxB, __shfl_xor_sync(0xffffffffu, mxB, 1));
        mxB = fmaxf(mxB, __shfl_xor_sync(0xffffffffu, mxB, 2));

        const float mnA = fmaxf(mA, mxA), mnB = fmaxf(mB, mxB);
        const float cA = exp2f(mA - mnA), cB = exp2f(mB - mnB);

        uint32_t pA[8], pB[8];
        float sumA = 0.f, sumB = 0.f;
        #pragma unroll
        for (int nt = 0; nt < 8; nt++) {
            pA[nt] = h2exp2(packh2(s[nt][0] - mnA, s[nt][1] - mnA));
            pB[nt] = h2exp2(packh2(s[nt][2] - mnB, s[nt][3] - mnB));
            float2 fA = h2f2(pA[nt]);
            float2 fB = h2f2(pB[nt]);
            sumA += fA.x + fA.y;
            sumB += fB.x + fB.y;
        }
        sumA += __shfl_xor_sync(0xffffffffu, sumA, 1);
        sumA += __shfl_xor_sync(0xffffffffu, sumA, 2);
        sumB += __shfl_xor_sync(0xffffffffu, sumB, 1);
        sumB += __shfl_xor_sync(0xffffffffu, sumB, 2);
        lA = lA * cA + sumA;  mA = mnA;
        lB = lB * cB + sumB;  mB = mnB;

        #pragma unroll
        for (int nt = 0; nt < 8; nt++) {
            o[nt][0] *= cA; o[nt][1] *= cA;
            o[nt][2] *= cB; o[nt][3] *= cB;
        }

        // ---- O += P @ V (A-frags are pA/pB) ----
        #pragma unroll
        for (int ks = 0; ks < 4; ks++) {
            uint32_t a[4] = {pA[2 * ks], pB[2 * ks], pA[2 * ks + 1], pB[2 * ks + 1]};
            #pragma unroll
            for (int ntp = 0; ntp < 4; ntp++) {
                uint32_t b00, b01, b10, b11;
                ldm_x4(b00, b01, b10, b11, vb_lane + ntp * (16 * FPB) + ks * 32);
                mma16(o[ntp * 2    ], a, b00, b01);
                mma16(o[ntp * 2 + 1], a, b10, b11);
            }
        }
    }

    // ---- epilogue: unnormalized partials ----
    const int rowA = b * SEQ + q0 + g;
    const int rowB = rowA + 8;
    float* poA = g_po + ((size_t)sp * MROWS + rowA) * DK;
    float* poB = g_po + ((size_t)sp * MROWS + rowB) * DK;
    #pragma unroll
    for (int nt = 0; nt < 8; nt++) {
        const int col = nt * 8 + 2 * t4;
        *(float2*)(poA + col) = make_float2(o[nt][0], o[nt][1]);
        *(float2*)(poB + col) = make_float2(o[nt][2], o[nt][3]);
    }
    if (t4 == 0) {
        g_pm[sp * MROWS + rowA] = mA;  g_pl[sp * MROWS + rowA] = lA;
        g_pm[sp * MROWS + rowB] = mB;  g_pl[sp * MROWS + rowB] = lB;
    }
}

// ============================================================
// Merge NSPLIT partials -> final output; 2 float4 per thread (ILP)
// ============================================================
__global__ __launch_bounds__(256) void merge_splits(float* __restrict__ out)
{
    const int i0 = (blockIdx.x * 256 + threadIdx.x) * 2;

    #pragma unroll
    for (int u = 0; u < 2; u++) {
        const int i = i0 + u;
        const int row = i >> 4, c4 = (i & 15) * 4;

        float m = -INFINITY;
        #pragma unroll
        for (int s = 0; s < NSPLIT; s++)
            m = fmaxf(m, g_pm[s * MROWS + row]);

        float lsum = 0.f;
        float4 acc = {0.f, 0.f, 0.f, 0.f};
        #pragma unroll
        for (int s = 0; s < NSPLIT; s++) {
            const float w = exp2f(g_pm[s * MROWS + row] - m);
            lsum += w * g_pl[s * MROWS + row];
            const float4 o = *(const float4*)(g_po + ((size_t)s * MROWS + row) * DK + c4);
            acc.x += w * o.x; acc.y += w * o.y;
            acc.z += w * o.z; acc.w += w * o.w;
        }
        const float inv = 1.f / lsum;
        float4 r = {acc.x * inv, acc.y * inv, acc.z * inv, acc.w * inv};
        *(float4*)(out + (size_t)row * DK + c4) = r;
    }
}

// ---------------- launch ----------------
extern "C" void kernel_launch(void* const* d_in, const int* in_sizes, int n_in,
                              void* d_out, int out_size)
{
    const float* input1 = (const float*)d_in[0];
    const float* input2 = (const float*)d_in[1];
    const float* Wq = (const float*)d_in[2];
    const float* bq = (const float*)d_in[3];
    const float* Wk = (const float*)d_in[4];
    const float* bk = (const float*)d_in[5];
    const float* Wv = (const float*)d_in[6];
    const float* bv = (const float*)d_in[7];
    float* out = (float*)d_out;

    (void)in_sizes; (void)n_in; (void)out_size;

    prep_w<<<192, 256>>>(Wq, Wk, Wv);

    dim3 pgrid(MROWS / 128, 1, 2);
    proj_fused<<<pgrid, 256>>>(input1, input2, bq, bk, bv);

    dim3 fgrid(SEQ / 64, BATCH, NSPLIT);
    flash_fp16<<<fgrid, 128>>>();

    merge_splits<<<(MROWS * 16) / 512, 256>>>(out);
}